// round 15
// baseline (speedup 1.0000x reference)
#include <cuda_runtime.h>
#include <cuda_bf16.h>
#include <cstdint>
#include <cstddef>

#define B_ 256
#define S_ 128
#define IN_ 64
#define H_ 512
#define W_ 512
#define G4 2048
#define NDEC 2560      // 2048 gate cols + 512 proj cols
#define KC 576         // concat K: 512 (h) + 64 (x)
#define RB 1152        // GLOBAL weight row bytes (576 bf16)
#define SRB 1168       // smem row stride: 73 x 16B (≡ 4 words mod 32 → conflict-free)
#define KQ 144         // per-k-warp K extent (9 k-steps of 16)

typedef __nv_bfloat16 bf16;

// ---------------- device globals ----------------
__device__ __align__(16) bf16 g_Menc[(size_t)NDEC * KC]; // gates(quad-perm): Whh|Wih ; proj: W1|0
__device__ float g_be[G4];
__device__ __align__(16) bf16 g_Mdec[(size_t)NDEC * KC]; // gates(quad-perm): Whh|Wih ; proj: W2|0
__device__ float g_bd[G4];
__device__ float g_c[B_ * H_];
__device__ __align__(16) bf16 g_hA[B_ * H_];
__device__ __align__(16) bf16 g_hB[B_ * H_];
__device__ __align__(16) bf16 g_hd0[B_ * H_];
__device__ __align__(16) bf16 g_hd1[B_ * H_];
__device__ float g_encproj[(size_t)S_ * B_ * W_];  // [s][b][w]
__device__ float g_hw2all[(size_t)S_ * B_ * W_];   // [t][b][w]
__device__ volatile unsigned g_barE[4 * 129];
__device__ volatile unsigned g_barD[4 * 129];

// ---------------- helpers ----------------
__device__ __forceinline__ float sigf(float x) { return 1.0f / (1.0f + __expf(-x)); }
__device__ __forceinline__ float fast_tanh(float x) {
    float y; asm("tanh.approx.f32 %0, %1;" : "=f"(y) : "f"(x)); return y;
}
__device__ __forceinline__ uint32_t smem_u32(const void* p) {
    uint32_t a;
    asm("{ .reg .u64 t; cvta.to.shared.u64 t, %1; cvt.u32.u64 %0, t; }" : "=r"(a) : "l"(p));
    return a;
}
__device__ __forceinline__ uint4 ldcg4u(const void* p) {
    uint4 v;
    asm volatile("ld.global.cg.v4.u32 {%0,%1,%2,%3}, [%4];"
        : "=r"(v.x), "=r"(v.y), "=r"(v.z), "=r"(v.w) : "l"(p));
    return v;
}
__device__ __forceinline__ void mma16(float* d, const uint32_t* a, const uint32_t* b) {
    asm volatile("mma.sync.aligned.m16n8k16.row.col.f32.bf16.bf16.f32 "
        "{%0,%1,%2,%3}, {%4,%5,%6,%7}, {%8,%9}, {%0,%1,%2,%3};"
        : "+f"(d[0]), "+f"(d[1]), "+f"(d[2]), "+f"(d[3])
        : "r"(a[0]), "r"(a[1]), "r"(a[2]), "r"(a[3]), "r"(b[0]), "r"(b[1]));
}
__device__ __forceinline__ void ldsm4(uint32_t* r, uint32_t addr) {
    asm volatile("ldmatrix.sync.aligned.m8n8.x4.shared.b16 {%0,%1,%2,%3}, [%4];"
        : "=r"(r[0]), "=r"(r[1]), "=r"(r[2]), "=r"(r[3]) : "r"(addr));
}
__device__ __forceinline__ void ldsm2(uint32_t* r, uint32_t addr) {
    asm volatile("ldmatrix.sync.aligned.m8n8.x2.shared.b16 {%0,%1}, [%2];"
        : "=r"(r[0]), "=r"(r[1]) : "r"(addr));
}
__device__ __forceinline__ void stlin(char* base, int row, int cc, uint4 v) {
    *(uint4*)(base + row * SRB + cc * 16) = v;
}
__device__ __forceinline__ uint4 packbf8(const float* p) {
    float4 a0 = *(const float4*)p, a1 = *(const float4*)(p + 4);
    __nv_bfloat162 p0 = __float22bfloat162_rn(make_float2(a0.x, a0.y));
    __nv_bfloat162 p1 = __float22bfloat162_rn(make_float2(a0.z, a0.w));
    __nv_bfloat162 p2 = __float22bfloat162_rn(make_float2(a1.x, a1.y));
    __nv_bfloat162 p3 = __float22bfloat162_rn(make_float2(a1.z, a1.w));
    uint4 v;
    v.x = *(uint32_t*)&p0; v.y = *(uint32_t*)&p1;
    v.z = *(uint32_t*)&p2; v.w = *(uint32_t*)&p3;
    return v;
}

// ---------------- prep ----------------
__global__ void k_prep(const float* __restrict__ Wih, const float* __restrict__ Whh,
                       const float* __restrict__ bih, const float* __restrict__ bhh,
                       const float* __restrict__ Wproj, bf16* __restrict__ M,
                       float* __restrict__ bias) {
    int q = blockIdx.x, k = threadIdx.x;   // q<2560, k<576
    float v;
    if (q < G4) {
        int r = (q & 3) * H_ + (q >> 2);
        v = (k < H_) ? Whh[(size_t)r * H_ + k] : Wih[(size_t)r * IN_ + (k - H_)];
        if (k == 0) bias[q] = bih[r] + bhh[r];
    } else {
        v = (k < H_) ? Wproj[(size_t)(q - G4) * H_ + k] : 0.0f;
    }
    M[(size_t)q * KC + k] = __float2bfloat16_rn(v);
}
__global__ void k_zero() {
    int i = blockIdx.x * blockDim.x + threadIdx.x;
    if (i < B_ * H_) g_hA[i] = __float2bfloat16_rn(0.0f);
    if (i < 4 * 129) { g_barE[i] = 0u; g_barD[i] = 0u; }
}

// ---------------- persistent chain (DEC=0 encoder, DEC=1 decoder) ----------------
// grid 128 = 4 m-groups x 32 n-blocks(80)
// 512 threads = 16 warps: (wmi 0..1)x(wn 0..1)x(wk 0..3); warp tile 32x40, K quartered per wk
template<int DEC>
__global__ __launch_bounds__(512)
void chain_kernel(const float* __restrict__ xg) {
    extern __shared__ char sm[];
    char* Ab = sm;                            // 64 rows x 1168B = 74752
    char* Bb = sm + 64 * SRB;                 // 80 rows x 1168B = 93440
    float* red0 = (float*)(sm + 144 * SRB);   // [4 tiles][40 regs][32 lanes] = 20480B
    float* red1 = red0 + 5120;                // same size
    int tid = threadIdx.x, lane = tid & 31, warp = tid >> 5;
    int wmi = warp & 1, wn = (warp >> 1) & 1, wk = warp >> 2;   // 2m x 2n x 4k
    int w4 = wmi * 2 + wn;                 // reduction tile id
    int gid = lane >> 2, tig = lane & 3;
    int mgrp = blockIdx.x & 3, nb = blockIdx.x >> 2;
    int m0 = mgrp * 64, n0 = nb * 80;
    bool pure = (n0 >= G4);                // proj-only CTA (produces no h)

    // resident weight tile [80 x 576]
    const bf16* Wp = DEC ? g_Mdec : g_Menc;
    const float* bp = DEC ? g_bd : g_be;
    for (int i = tid; i < 80 * 72; i += 512) {
        int row = i / 72, cc = i % 72;
        uint4 v = *(const uint4*)((const char*)Wp + (size_t)(n0 + row) * RB + cc * 16);
        stlin(Bb, row, cc, v);
    }

    // register caches (wk==0 warps own the epilogue)
    float4 bias4[5];
    float creg[2][5];
    if (wk == 0) {
        #pragma unroll
        for (int nt = 0; nt < 5; nt++) {
            int fb = n0 + wn * 40 + nt * 8;
            if (fb < G4) {
                int j = (fb >> 2) + (tig >> 1);
                bias4[nt] = *(const float4*)&bp[4 * j];
                int p = tig & 1;
                #pragma unroll
                for (int mt = 0; mt < 2; mt++) {
                    int r = m0 + wmi * 32 + mt * 16 + gid + (p ? 8 : 0);
                    creg[mt][nt] = DEC ? g_c[(size_t)r * H_ + j] : 0.0f;
                }
            }
        }
    }
    // decoder: constant x-part (dec_in) loaded once (chunks 64..71)
    if (DEC) {
        for (int i = tid; i < 64 * 8; i += 512) {
            int row = i >> 3, c8 = i & 7;
            stlin(Ab, row, 64 + c8, packbf8(xg + (size_t)(m0 + row) * IN_ + c8 * 8));
        }
    }
    __syncthreads();

    // ---- precomputed LDSM lane addresses (affine in k-step) ----
    int l7 = lane & 7;
    uint32_t AbU = smem_u32(Ab), BbU = smem_u32(Bb);
    // A m-frag rows 0-15 of this warp's 32-row tile
    uint32_t aBase0 = AbU + (uint32_t)(wmi * 32 + ((lane >> 3) & 1) * 8 + l7) * SRB
                          + (uint32_t)(wk * 9 * 2 + (lane >> 4)) * 16;
    uint32_t aBase1 = aBase0 + 16 * SRB;    // rows 16-31
    // B x4 (n-frags 0,1)
    uint32_t bBase0 = BbU + (uint32_t)(wn * 40 + (lane >> 4) * 8 + l7) * SRB
                          + (uint32_t)(wk * 9 * 2 + ((lane >> 3) & 1)) * 16;
    uint32_t bBase1 = bBase0 + 16 * SRB;    // n-frags 2,3
    // B x2 (n-frag 4)
    uint32_t bBase2 = BbU + (uint32_t)(wn * 40 + 32 + l7) * SRB
                          + (uint32_t)(wk * 9 * 2 + ((lane >> 3) & 1)) * 16;

    volatile unsigned* bar = DEC ? g_barD : g_barE;

    for (int st = 0; st < 129; st++) {
        const bf16* A;
        bf16* hout;
        if (DEC) {
            A = (st == 0) ? g_hA : ((st & 1) ? g_hd0 : g_hd1);
            hout = (st & 1) ? g_hd1 : g_hd0;
        } else {
            A = (st & 1) ? g_hB : g_hA;
            hout = (st & 1) ? g_hA : g_hB;
        }
        // h part (chunks 0..63)
        for (int i = tid; i < 64 * 64; i += 512) {
            int row = i >> 6, cc = i & 63;
            uint4 v = ldcg4u((const char*)A + (size_t)(m0 + row) * 1024 + cc * 16);
            stlin(Ab, row, cc, v);
        }
        // encoder: x_t part (chunks 64..71)
        if (!DEC) {
            int t = (st < S_) ? st : (S_ - 1);
            for (int i = tid; i < 64 * 8; i += 512) {
                int row = i >> 3, c8 = i & 7;
                stlin(Ab, row, 64 + c8,
                      packbf8(xg + ((size_t)(m0 + row) * S_ + t) * IN_ + c8 * 8));
            }
        }
        __syncthreads();

        // proj-only CTAs: A consumed into smem -> arrive now (WAR-safe)
        if (pure && st < 128 && tid == 0)
            atomicAdd((unsigned*)&bar[st * 4 + mgrp], 1u);

        float acc[2][5][4];
        #pragma unroll
        for (int a = 0; a < 2; a++)
            #pragma unroll
            for (int b = 0; b < 5; b++)
                #pragma unroll
                for (int c = 0; c < 4; c++) acc[a][b][c] = 0.0f;

        #pragma unroll
        for (int ks = 0; ks < 9; ks++) {
            uint32_t af0[4], af1[4], bfr[5][2];
            ldsm4(af0, aBase0 + ks * 32);
            ldsm4(af1, aBase1 + ks * 32);
            ldsm4(&bfr[0][0], bBase0 + ks * 32);
            ldsm4(&bfr[2][0], bBase1 + ks * 32);
            ldsm2(bfr[4], bBase2 + ks * 32);
            #pragma unroll
            for (int nt = 0; nt < 5; nt++) {
                mma16(acc[0][nt], af0, bfr[nt]);
                mma16(acc[1][nt], af1, bfr[nt]);
            }
        }

        // ---- 2-round k reduction: (wk1->wk0, wk3->wk2) then wk2->wk0 ----
        if (wk == 1 || wk == 3) {
            float* buf = (wk == 1) ? red0 : red1;
            #pragma unroll
            for (int mt = 0; mt < 2; mt++)
                #pragma unroll
                for (int nt = 0; nt < 5; nt++)
                    #pragma unroll
                    for (int c = 0; c < 4; c++)
                        buf[((w4 * 40 + mt * 20 + nt * 4 + c) << 5) + lane] = acc[mt][nt][c];
        }
        __syncthreads();
        if (wk == 0) {
            #pragma unroll
            for (int mt = 0; mt < 2; mt++)
                #pragma unroll
                for (int nt = 0; nt < 5; nt++)
                    #pragma unroll
                    for (int c = 0; c < 4; c++)
                        acc[mt][nt][c] += red0[((w4 * 40 + mt * 20 + nt * 4 + c) << 5) + lane];
        } else if (wk == 2) {
            #pragma unroll
            for (int mt = 0; mt < 2; mt++)
                #pragma unroll
                for (int nt = 0; nt < 5; nt++)
                    #pragma unroll
                    for (int c = 0; c < 4; c++) {
                        int idx = ((w4 * 40 + mt * 20 + nt * 4 + c) << 5) + lane;
                        red1[idx] += acc[mt][nt][c];   // read-then-write same thread
                    }
        }
        __syncthreads();
        if (wk == 0) {
            #pragma unroll
            for (int mt = 0; mt < 2; mt++)
                #pragma unroll
                for (int nt = 0; nt < 5; nt++)
                    #pragma unroll
                    for (int c = 0; c < 4; c++)
                        acc[mt][nt][c] += red1[((w4 * 40 + mt * 20 + nt * 4 + c) << 5) + lane];

            // ---- epilogue (wk0 warps only) ----
            #pragma unroll
            for (int mt = 0; mt < 2; mt++) {
                #pragma unroll
                for (int nt = 0; nt < 5; nt++) {
                    int fb = n0 + wn * 40 + nt * 8;     // warp-uniform
                    float c0 = acc[mt][nt][0], c1 = acc[mt][nt][1];
                    float c2 = acc[mt][nt][2], c3 = acc[mt][nt][3];
                    int rr = m0 + wmi * 32 + mt * 16 + gid;
                    if (fb < G4) {
                        if (st >= S_) continue;
                        float x0 = __shfl_xor_sync(0xFFFFFFFFu, c0, 1);
                        float x1 = __shfl_xor_sync(0xFFFFFFFFu, c1, 1);
                        float x2 = __shfl_xor_sync(0xFFFFFFFFu, c2, 1);
                        float x3 = __shfl_xor_sync(0xFFFFFFFFu, c3, 1);
                        int p = tig & 1;
                        int r = rr + (p ? 8 : 0);
                        int j = (fb >> 2) + (tig >> 1);
                        float gi = p ? x2 : c0;
                        float gf = p ? x3 : c1;
                        float gg = p ? c2 : x0;
                        float go = p ? c3 : x1;
                        float4 xa = bias4[nt];
                        float i_ = sigf(gi + xa.x);
                        float f_ = sigf(gf + xa.y);
                        float g_ = tanhf(gg + xa.z);
                        float o_ = sigf(go + xa.w);
                        float cn = f_ * creg[mt][nt] + i_ * g_;   // DEC: c fixed at c_last
                        if (!DEC) {
                            creg[mt][nt] = cn;
                            if (st == S_ - 1) g_c[(size_t)r * H_ + j] = cn;
                        }
                        hout[(size_t)r * H_ + j] = __float2bfloat16_rn(o_ * tanhf(cn));
                    } else {
                        if (st == 0) continue;
                        int cc = fb + 2 * tig - G4;
                        float* dst = DEC ? g_hw2all : g_encproj;
                        size_t base = ((size_t)(st - 1) * B_ + rr) * W_;
                        *(float2*)&dst[base + cc]                  = make_float2(c0, c1);
                        *(float2*)&dst[base + (size_t)8 * W_ + cc] = make_float2(c2, c3);
                    }
                }
            }
        }

        // step barrier
        if (st < 128) {
            volatile unsigned* slot = &bar[st * 4 + mgrp];
            __syncthreads();
            if (tid == 0) {
                if (!pure) {                       // producers: fence + arrive late
                    __threadfence();
                    atomicAdd((unsigned*)slot, 1u);
                }
                while (*slot < 32u) { asm volatile("nanosleep.u32 32;"); }
                __threadfence();
            }
            __syncthreads();
        }
    }
}

// ---------------- mega attention + log_softmax ----------------
__global__ __launch_bounds__(256)
void attn_mega(const float* __restrict__ vt, float* __restrict__ out) {
    __shared__ float hw2s[16 * 512];
    __shared__ float sc[16 * 128];
    int b = blockIdx.x, t0 = blockIdx.y * 16;
    int tid = threadIdx.x, lane = tid & 31, w = tid >> 5;

    for (int i = tid * 4; i < 16 * 512; i += 256 * 4) {
        int t = i >> 9, c = i & 511;
        *(float4*)&hw2s[i] = *(const float4*)&g_hw2all[((size_t)(t0 + t) * B_ + b) * W_ + c];
    }
    float4 vv[4];
    #pragma unroll
    for (int j = 0; j < 4; j++) vv[j] = *(const float4*)&vt[j * 128 + lane * 4];
    __syncthreads();

    float4 er[4], ern[4];
    {
        const float* ep = &g_encproj[((size_t)w * B_ + b) * W_];
        #pragma unroll
        for (int j = 0; j < 4; j++) er[j] = *(const float4*)&ep[j * 128 + lane * 4];
    }
    for (int si = 0; si < 16; si++) {
        int s = si * 8 + w;
        if (si < 15) {
            const float* ep = &g_encproj[((size_t)(s + 8) * B_ + b) * W_];
            #pragma unroll
            for (int j = 0; j < 4; j++) ern[j] = *(const float4*)&ep[j * 128 + lane * 4];
        }
        #pragma unroll 4
        for (int tl = 0; tl < 16; tl++) {
            float a = 0.0f;
            #pragma unroll
            for (int j = 0; j < 4; j++) {
                float4 hv = *(const float4*)&hw2s[tl * 512 + j * 128 + lane * 4];
                a += fast_tanh(er[j].x + hv.x) * vv[j].x;
                a += fast_tanh(er[j].y + hv.y) * vv[j].y;
                a += fast_tanh(er[j].z + hv.z) * vv[j].z;
                a += fast_tanh(er[j].w + hv.w) * vv[j].w;
            }
            #pragma unroll
            for (int off = 16; off; off >>= 1) a += __shfl_xor_sync(0xFFFFFFFFu, a, off);
            if (lane == 0) sc[tl * 128 + s] = a;
        }
        #pragma unroll
        for (int j = 0; j < 4; j++) er[j] = ern[j];
    }
    __syncthreads();

    for (int tl = w; tl < 16; tl += 8) {
        float4 v = *(const float4*)&sc[tl * 128 + lane * 4];
        float m = fmaxf(fmaxf(v.x, v.y), fmaxf(v.z, v.w));
        #pragma unroll
        for (int off = 16; off; off >>= 1) m = fmaxf(m, __shfl_xor_sync(0xFFFFFFFFu, m, off));
        float e = __expf(v.x - m) + __expf(v.y - m) + __expf(v.z - m) + __expf(v.w - m);
        #pragma unroll
        for (int off = 16; off; off >>= 1) e += __shfl_xor_sync(0xFFFFFFFFu, e, off);
        float L = m + logf(e);
        float4 o = make_float4(v.x - L, v.y - L, v.z - L, v.w - L);
        *(float4*)&out[((size_t)b * S_ + (t0 + tl)) * S_ + lane * 4] = o;
    }
}

// ---------------- launch ----------------
extern "C" void kernel_launch(void* const* d_in, const int* in_sizes, int n_in,
                              void* d_out, int out_size) {
    const float* x        = (const float*)d_in[0];
    const float* dec_in   = (const float*)d_in[1];
    const float* W_ih_enc = (const float*)d_in[2];
    const float* W_hh_enc = (const float*)d_in[3];
    const float* b_ih_enc = (const float*)d_in[4];
    const float* b_hh_enc = (const float*)d_in[5];
    const float* W_ih_dec = (const float*)d_in[6];
    const float* W_hh_dec = (const float*)d_in[7];
    const float* b_ih_dec = (const float*)d_in[8];
    const float* b_hh_dec = (const float*)d_in[9];
    const float* W1       = (const float*)d_in[10];
    const float* W2       = (const float*)d_in[11];
    const float* vt       = (const float*)d_in[12];
    float* out = (float*)d_out;

    void *p_Menc, *p_Mdec, *p_be, *p_bd;
    cudaGetSymbolAddress(&p_Menc, g_Menc);
    cudaGetSymbolAddress(&p_Mdec, g_Mdec);
    cudaGetSymbolAddress(&p_be,   g_be);
    cudaGetSymbolAddress(&p_bd,   g_bd);

    const int CHAIN_SM = 144 * SRB + 2 * 20480;   // 209,152
    cudaFuncSetAttribute(chain_kernel<0>, cudaFuncAttributeMaxDynamicSharedMemorySize, CHAIN_SM);
    cudaFuncSetAttribute(chain_kernel<1>, cudaFuncAttributeMaxDynamicSharedMemorySize, CHAIN_SM);

    k_prep<<<NDEC, KC>>>(W_ih_enc, W_hh_enc, b_ih_enc, b_hh_enc, W1,
                         (bf16*)p_Menc, (float*)p_be);
    k_prep<<<NDEC, KC>>>(W_ih_dec, W_hh_dec, b_ih_dec, b_hh_dec, W2,
                         (bf16*)p_Mdec, (float*)p_bd);
    k_zero<<<(B_ * H_ + 255) / 256, 256>>>();

    chain_kernel<0><<<128, 512, CHAIN_SM>>>(x);        // encoder + enc_proj
    chain_kernel<1><<<128, 512, CHAIN_SM>>>(dec_in);   // decoder + hw2

    attn_mega<<<dim3(B_, 8), 256>>>(vt, out);

    (void)in_sizes; (void)n_in; (void)out_size;
}

// round 16
// speedup vs baseline: 1.1934x; 1.1934x over previous
#include <cuda_runtime.h>
#include <cuda_bf16.h>
#include <cstdint>
#include <cstddef>

#define B_ 256
#define S_ 128
#define IN_ 64
#define H_ 512
#define W_ 512
#define G4 2048
#define NDEC 2560      // 2048 gate cols + 512 proj cols
#define KC 576         // concat K: 512 (h) + 64 (x)
#define RB 1152        // GLOBAL weight row bytes (576 bf16)
#define SRB 1168       // smem row stride: 73 x 16B (≡ 4 words mod 32 → conflict-free)

typedef __nv_bfloat16 bf16;

// ---------------- device globals ----------------
__device__ __align__(16) bf16 g_Menc[(size_t)NDEC * KC]; // gates(quad-perm): Whh|Wih ; proj: W1|0
__device__ float g_be[G4];
__device__ __align__(16) bf16 g_Mdec[(size_t)NDEC * KC]; // gates(quad-perm): Whh|Wih ; proj: W2|0
__device__ float g_bd[G4];
__device__ float g_c[B_ * H_];
__device__ __align__(16) bf16 g_xb[(size_t)B_ * S_ * IN_];  // prepacked bf16 x
__device__ __align__(16) bf16 g_hA[B_ * H_];
__device__ __align__(16) bf16 g_hB[B_ * H_];
__device__ __align__(16) bf16 g_hd0[B_ * H_];
__device__ __align__(16) bf16 g_hd1[B_ * H_];
__device__ float g_encproj[(size_t)S_ * B_ * W_];  // [s][b][w]
__device__ float g_hw2all[(size_t)S_ * B_ * W_];   // [t][b][w]
__device__ volatile unsigned g_barE[4 * 129];
__device__ volatile unsigned g_barD[4 * 129];

// ---------------- helpers ----------------
__device__ __forceinline__ float sigf(float x) { return 1.0f / (1.0f + __expf(-x)); }
__device__ __forceinline__ float fast_tanh(float x) {
    float y; asm("tanh.approx.f32 %0, %1;" : "=f"(y) : "f"(x)); return y;
}
__device__ __forceinline__ uint32_t smem_u32(const void* p) {
    uint32_t a;
    asm("{ .reg .u64 t; cvta.to.shared.u64 t, %1; cvt.u32.u64 %0, t; }" : "=r"(a) : "l"(p));
    return a;
}
__device__ __forceinline__ uint4 ldcg4u(const void* p) {
    uint4 v;
    asm volatile("ld.global.cg.v4.u32 {%0,%1,%2,%3}, [%4];"
        : "=r"(v.x), "=r"(v.y), "=r"(v.z), "=r"(v.w) : "l"(p));
    return v;
}
__device__ __forceinline__ void mma16(float* d, const uint32_t* a, const uint32_t* b) {
    asm volatile("mma.sync.aligned.m16n8k16.row.col.f32.bf16.bf16.f32 "
        "{%0,%1,%2,%3}, {%4,%5,%6,%7}, {%8,%9}, {%0,%1,%2,%3};"
        : "+f"(d[0]), "+f"(d[1]), "+f"(d[2]), "+f"(d[3])
        : "r"(a[0]), "r"(a[1]), "r"(a[2]), "r"(a[3]), "r"(b[0]), "r"(b[1]));
}
__device__ __forceinline__ void ldsm4(uint32_t* r, uint32_t addr) {
    asm volatile("ldmatrix.sync.aligned.m8n8.x4.shared.b16 {%0,%1,%2,%3}, [%4];"
        : "=r"(r[0]), "=r"(r[1]), "=r"(r[2]), "=r"(r[3]) : "r"(addr));
}
__device__ __forceinline__ void ldsm2(uint32_t* r, uint32_t addr) {
    asm volatile("ldmatrix.sync.aligned.m8n8.x2.shared.b16 {%0,%1}, [%2];"
        : "=r"(r[0]), "=r"(r[1]) : "r"(addr));
}
__device__ __forceinline__ void stlin(char* base, int row, int cc, uint4 v) {
    *(uint4*)(base + row * SRB + cc * 16) = v;
}
__device__ __forceinline__ uint4 packbf8(const float* p) {
    float4 a0 = *(const float4*)p, a1 = *(const float4*)(p + 4);
    __nv_bfloat162 p0 = __float22bfloat162_rn(make_float2(a0.x, a0.y));
    __nv_bfloat162 p1 = __float22bfloat162_rn(make_float2(a0.z, a0.w));
    __nv_bfloat162 p2 = __float22bfloat162_rn(make_float2(a1.x, a1.y));
    __nv_bfloat162 p3 = __float22bfloat162_rn(make_float2(a1.z, a1.w));
    uint4 v;
    v.x = *(uint32_t*)&p0; v.y = *(uint32_t*)&p1;
    v.z = *(uint32_t*)&p2; v.w = *(uint32_t*)&p3;
    return v;
}

// ---------------- prep ----------------
__global__ void k_prep(const float* __restrict__ Wih, const float* __restrict__ Whh,
                       const float* __restrict__ bih, const float* __restrict__ bhh,
                       const float* __restrict__ Wproj, bf16* __restrict__ M,
                       float* __restrict__ bias) {
    int q = blockIdx.x, k = threadIdx.x;   // q<2560, k<576
    float v;
    if (q < G4) {
        int r = (q & 3) * H_ + (q >> 2);
        v = (k < H_) ? Whh[(size_t)r * H_ + k] : Wih[(size_t)r * IN_ + (k - H_)];
        if (k == 0) bias[q] = bih[r] + bhh[r];
    } else {
        v = (k < H_) ? Wproj[(size_t)(q - G4) * H_ + k] : 0.0f;
    }
    M[(size_t)q * KC + k] = __float2bfloat16_rn(v);
}
__global__ void k_packx(const float* __restrict__ x) {
    int i = blockIdx.x * blockDim.x + threadIdx.x;
    if (i < B_ * S_ * IN_) g_xb[i] = __float2bfloat16_rn(x[i]);
}
__global__ void k_zero() {
    int i = blockIdx.x * blockDim.x + threadIdx.x;
    if (i < B_ * H_) g_hA[i] = __float2bfloat16_rn(0.0f);
    if (i < 4 * 129) { g_barE[i] = 0u; g_barD[i] = 0u; }
}

// ---------------- persistent chain (DEC=0 encoder, DEC=1 decoder) ----------------
// grid 128 = 4 m-groups x 32 n-blocks(80)
// 512 threads = 16 warps: (wmi 0..3) x (wn 0..1) x (wk 0..1); warp tile 16x40, K halved per wk
// epilogue split: wk0 owns n-frags {0,1,2}; wk1 owns {3,4}
template<int DEC>
__global__ __launch_bounds__(512)
void chain_kernel(const float* __restrict__ xg) {
    extern __shared__ char sm[];
    char* Ab = sm;                            // 64 rows x 1168B = 74752
    char* Bb = sm + 64 * SRB;                 // 80 rows x 1168B = 93440
    float* red = (float*)(sm + 144 * SRB);    // [20][256] = 20480
    int tid = threadIdx.x, lane = tid & 31, warp = tid >> 5;
    int wmi = warp >> 2, wn = (warp >> 1) & 1, wk = warp & 1;
    int w8 = wmi * 2 + wn;                 // 0..7 exchange column group
    int gid = lane >> 2, tig = lane & 3;
    int mgrp = blockIdx.x & 3, nb = blockIdx.x >> 2;
    int m0 = mgrp * 64, n0 = nb * 80;
    bool pure = (n0 >= G4);                // proj-only CTA (produces no h)
    int ntlo = wk ? 3 : 0, nthi = wk ? 5 : 3;   // owned epilogue frags

    // resident weight tile [80 x 576]
    const bf16* Wp = DEC ? g_Mdec : g_Menc;
    const float* bp = DEC ? g_bd : g_be;
    for (int i = tid; i < 80 * 72; i += 512) {
        int row = i / 72, cc = i % 72;
        uint4 v = *(const uint4*)((const char*)Wp + (size_t)(n0 + row) * RB + cc * 16);
        stlin(Bb, row, cc, v);
    }

    // register caches for OWNED frags only
    float4 bias4[5];
    float creg[5];
    #pragma unroll
    for (int nt = 0; nt < 5; nt++) {
        if (nt < ntlo || nt >= nthi) continue;
        int fb = n0 + wn * 40 + nt * 8;
        if (fb < G4) {
            int j = (fb >> 2) + (tig >> 1);
            bias4[nt] = *(const float4*)&bp[4 * j];
            int p = tig & 1;
            int r = m0 + wmi * 16 + gid + (p ? 8 : 0);
            creg[nt] = DEC ? g_c[(size_t)r * H_ + j] : 0.0f;
        }
    }
    // decoder: constant x-part (dec_in) loaded once (chunks 64..71)
    if (DEC) {
        for (int i = tid; i < 64 * 8; i += 512) {
            int row = i >> 3, c8 = i & 7;
            stlin(Ab, row, 64 + c8, packbf8(xg + (size_t)(m0 + row) * IN_ + c8 * 8));
        }
    }
    __syncthreads();

    // ---- precomputed LDSM lane addresses (affine in k-step) ----
    int l7 = lane & 7;
    uint32_t AbU = smem_u32(Ab), BbU = smem_u32(Bb);
    uint32_t aBase = AbU + (uint32_t)(wmi * 16 + ((lane >> 3) & 1) * 8 + l7) * SRB
                         + (uint32_t)(wk * 36 + (lane >> 4)) * 16;
    uint32_t bBase0 = BbU + (uint32_t)(wn * 40 + (lane >> 4) * 8 + l7) * SRB
                          + (uint32_t)(wk * 36 + ((lane >> 3) & 1)) * 16;
    uint32_t bBase1 = bBase0 + 16 * SRB;            // n-frags 2,3
    uint32_t bBase2 = BbU + (uint32_t)(wn * 40 + 32 + l7) * SRB
                          + (uint32_t)(wk * 36 + ((lane >> 3) & 1)) * 16;

    volatile unsigned* bar = DEC ? g_barD : g_barE;

    for (int st = 0; st < 129; st++) {
        const bf16* A;
        bf16* hout;
        if (DEC) {
            A = (st == 0) ? g_hA : ((st & 1) ? g_hd0 : g_hd1);
            hout = (st & 1) ? g_hd1 : g_hd0;
        } else {
            A = (st & 1) ? g_hB : g_hA;
            hout = (st & 1) ? g_hA : g_hB;
        }
        // h part (chunks 0..63)
        for (int i = tid; i < 64 * 64; i += 512) {
            int row = i >> 6, cc = i & 63;
            uint4 v = ldcg4u((const char*)A + (size_t)(m0 + row) * 1024 + cc * 16);
            stlin(Ab, row, cc, v);
        }
        // encoder: x_t part (chunks 64..71) from prepacked bf16 (1 chunk/thread)
        if (!DEC) {
            int t = (st < S_) ? st : (S_ - 1);
            int row = tid >> 3, c8 = tid & 7;
            uint4 v = *(const uint4*)((const char*)g_xb +
                          ((size_t)(m0 + row) * S_ + t) * 128 + c8 * 16);
            stlin(Ab, row, 64 + c8, v);
        }
        __syncthreads();

        // proj-only CTAs: A consumed into smem -> arrive now (WAR-safe)
        if (pure && st < 128 && tid == 0)
            atomicAdd((unsigned*)&bar[st * 4 + mgrp], 1u);

        float acc[5][4];
        #pragma unroll
        for (int b = 0; b < 5; b++)
            #pragma unroll
            for (int c = 0; c < 4; c++) acc[b][c] = 0.0f;

        #pragma unroll
        for (int ks = 0; ks < 18; ks++) {
            uint32_t af[4], bfr[5][2];
            ldsm4(af, aBase + ks * 32);
            ldsm4(&bfr[0][0], bBase0 + ks * 32);
            ldsm4(&bfr[2][0], bBase1 + ks * 32);
            ldsm2(bfr[4], bBase2 + ks * 32);
            #pragma unroll
            for (int nt = 0; nt < 5; nt++) mma16(acc[nt], af, bfr[nt]);
        }

        // ---- cross-k exchange: write partials of NON-owned frags ----
        if (wk == 1) {
            #pragma unroll
            for (int nt = 0; nt < 3; nt++)
                #pragma unroll
                for (int c = 0; c < 4; c++)
                    red[(nt * 4 + c) * 256 + w8 * 32 + lane] = acc[nt][c];
        } else {
            #pragma unroll
            for (int nt = 3; nt < 5; nt++)
                #pragma unroll
                for (int c = 0; c < 4; c++)
                    red[(nt * 4 + c) * 256 + w8 * 32 + lane] = acc[nt][c];
        }
        __syncthreads();

        // reduce owned frags + epilogue (both wk halves in parallel)
        #pragma unroll
        for (int nt = 0; nt < 5; nt++) {
            if (nt < ntlo || nt >= nthi) continue;
            #pragma unroll
            for (int c = 0; c < 4; c++)
                acc[nt][c] += red[(nt * 4 + c) * 256 + w8 * 32 + lane];
        }
        #pragma unroll
        for (int nt = 0; nt < 5; nt++) {
            if (nt < ntlo || nt >= nthi) continue;
            int fb = n0 + wn * 40 + nt * 8;     // warp-uniform
            float c0 = acc[nt][0], c1 = acc[nt][1];
            float c2 = acc[nt][2], c3 = acc[nt][3];
            int rr = m0 + wmi * 16 + gid;
            if (fb < G4) {
                if (st >= S_) continue;
                float x0 = __shfl_xor_sync(0xFFFFFFFFu, c0, 1);
                float x1 = __shfl_xor_sync(0xFFFFFFFFu, c1, 1);
                float x2 = __shfl_xor_sync(0xFFFFFFFFu, c2, 1);
                float x3 = __shfl_xor_sync(0xFFFFFFFFu, c3, 1);
                int p = tig & 1;
                int r = rr + (p ? 8 : 0);
                int j = (fb >> 2) + (tig >> 1);
                float gi = p ? x2 : c0;
                float gf = p ? x3 : c1;
                float gg = p ? c2 : x0;
                float go = p ? c3 : x1;
                float4 xa = bias4[nt];
                float i_ = sigf(gi + xa.x);
                float f_ = sigf(gf + xa.y);
                float g_ = tanhf(gg + xa.z);
                float o_ = sigf(go + xa.w);
                float cn = f_ * creg[nt] + i_ * g_;    // DEC: c fixed at c_last
                if (!DEC) {
                    creg[nt] = cn;
                    if (st == S_ - 1) g_c[(size_t)r * H_ + j] = cn;
                }
                hout[(size_t)r * H_ + j] = __float2bfloat16_rn(o_ * tanhf(cn));
            } else {
                if (st == 0) continue;
                int cc = fb + 2 * tig - G4;
                float* dst = DEC ? g_hw2all : g_encproj;
                size_t base = ((size_t)(st - 1) * B_ + rr) * W_;
                *(float2*)&dst[base + cc]                  = make_float2(c0, c1);
                *(float2*)&dst[base + (size_t)8 * W_ + cc] = make_float2(c2, c3);
            }
        }

        // step barrier
        if (st < 128) {
            volatile unsigned* slot = &bar[st * 4 + mgrp];
            __syncthreads();
            if (tid == 0) {
                if (!pure) {                       // producers: fence + arrive late
                    __threadfence();
                    atomicAdd((unsigned*)slot, 1u);
                }
                int tries = 0;
                while (*slot < 32u) {
                    if (++tries > 128) asm volatile("nanosleep.u32 32;");
                }
                __threadfence();
            }
            __syncthreads();
        }
    }
}

// ---------------- mega attention + log_softmax ----------------
__global__ __launch_bounds__(256)
void attn_mega(const float* __restrict__ vt, float* __restrict__ out) {
    __shared__ float hw2s[16 * 512];
    __shared__ float sc[16 * 128];
    int b = blockIdx.x, t0 = blockIdx.y * 16;
    int tid = threadIdx.x, lane = tid & 31, w = tid >> 5;

    for (int i = tid * 4; i < 16 * 512; i += 256 * 4) {
        int t = i >> 9, c = i & 511;
        *(float4*)&hw2s[i] = *(const float4*)&g_hw2all[((size_t)(t0 + t) * B_ + b) * W_ + c];
    }
    float4 vv[4];
    #pragma unroll
    for (int j = 0; j < 4; j++) vv[j] = *(const float4*)&vt[j * 128 + lane * 4];
    __syncthreads();

    float4 er[4], ern[4];
    {
        const float* ep = &g_encproj[((size_t)w * B_ + b) * W_];
        #pragma unroll
        for (int j = 0; j < 4; j++) er[j] = *(const float4*)&ep[j * 128 + lane * 4];
    }
    for (int si = 0; si < 16; si++) {
        int s = si * 8 + w;
        if (si < 15) {
            const float* ep = &g_encproj[((size_t)(s + 8) * B_ + b) * W_];
            #pragma unroll
            for (int j = 0; j < 4; j++) ern[j] = *(const float4*)&ep[j * 128 + lane * 4];
        }
        #pragma unroll 4
        for (int tl = 0; tl < 16; tl++) {
            float a = 0.0f;
            #pragma unroll
            for (int j = 0; j < 4; j++) {
                float4 hv = *(const float4*)&hw2s[tl * 512 + j * 128 + lane * 4];
                a += fast_tanh(er[j].x + hv.x) * vv[j].x;
                a += fast_tanh(er[j].y + hv.y) * vv[j].y;
                a += fast_tanh(er[j].z + hv.z) * vv[j].z;
                a += fast_tanh(er[j].w + hv.w) * vv[j].w;
            }
            #pragma unroll
            for (int off = 16; off; off >>= 1) a += __shfl_xor_sync(0xFFFFFFFFu, a, off);
            if (lane == 0) sc[tl * 128 + s] = a;
        }
        #pragma unroll
        for (int j = 0; j < 4; j++) er[j] = ern[j];
    }
    __syncthreads();

    for (int tl = w; tl < 16; tl += 8) {
        float4 v = *(const float4*)&sc[tl * 128 + lane * 4];
        float m = fmaxf(fmaxf(v.x, v.y), fmaxf(v.z, v.w));
        #pragma unroll
        for (int off = 16; off; off >>= 1) m = fmaxf(m, __shfl_xor_sync(0xFFFFFFFFu, m, off));
        float e = __expf(v.x - m) + __expf(v.y - m) + __expf(v.z - m) + __expf(v.w - m);
        #pragma unroll
        for (int off = 16; off; off >>= 1) e += __shfl_xor_sync(0xFFFFFFFFu, e, off);
        float L = m + logf(e);
        float4 o = make_float4(v.x - L, v.y - L, v.z - L, v.w - L);
        *(float4*)&out[((size_t)b * S_ + (t0 + tl)) * S_ + lane * 4] = o;
    }
}

// ---------------- launch ----------------
extern "C" void kernel_launch(void* const* d_in, const int* in_sizes, int n_in,
                              void* d_out, int out_size) {
    const float* x        = (const float*)d_in[0];
    const float* dec_in   = (const float*)d_in[1];
    const float* W_ih_enc = (const float*)d_in[2];
    const float* W_hh_enc = (const float*)d_in[3];
    const float* b_ih_enc = (const float*)d_in[4];
    const float* b_hh_enc = (const float*)d_in[5];
    const float* W_ih_dec = (const float*)d_in[6];
    const float* W_hh_dec = (const float*)d_in[7];
    const float* b_ih_dec = (const float*)d_in[8];
    const float* b_hh_dec = (const float*)d_in[9];
    const float* W1       = (const float*)d_in[10];
    const float* W2       = (const float*)d_in[11];
    const float* vt       = (const float*)d_in[12];
    float* out = (float*)d_out;

    void *p_Menc, *p_Mdec, *p_be, *p_bd;
    cudaGetSymbolAddress(&p_Menc, g_Menc);
    cudaGetSymbolAddress(&p_Mdec, g_Mdec);
    cudaGetSymbolAddress(&p_be,   g_be);
    cudaGetSymbolAddress(&p_bd,   g_bd);

    const int CHAIN_SM = 144 * SRB + 20480;   // 188,672
    cudaFuncSetAttribute(chain_kernel<0>, cudaFuncAttributeMaxDynamicSharedMemorySize, CHAIN_SM);
    cudaFuncSetAttribute(chain_kernel<1>, cudaFuncAttributeMaxDynamicSharedMemorySize, CHAIN_SM);

    k_prep<<<NDEC, KC>>>(W_ih_enc, W_hh_enc, b_ih_enc, b_hh_enc, W1,
                         (bf16*)p_Menc, (float*)p_be);
    k_prep<<<NDEC, KC>>>(W_ih_dec, W_hh_dec, b_ih_dec, b_hh_dec, W2,
                         (bf16*)p_Mdec, (float*)p_bd);
    k_packx<<<(B_ * S_ * IN_ + 511) / 512, 512>>>(x);
    k_zero<<<(B_ * H_ + 255) / 256, 256>>>();

    chain_kernel<0><<<128, 512, CHAIN_SM>>>(x);        // encoder + enc_proj
    chain_kernel<1><<<128, 512, CHAIN_SM>>>(dec_in);   // decoder + hw2

    attn_mega<<<dim3(B_, 8), 256>>>(vt, out);

    (void)in_sizes; (void)n_in; (void)out_size;
}